// round 16
// baseline (speedup 1.0000x reference)
#include <cuda_runtime.h>
#include <cuda_fp16.h>

#define NN 100000
#define EE 800000
#define HH 128
#define GG 64
#define LL 4

typedef unsigned int u32;
typedef unsigned short u16;

// ------------------ static device scratch ------------------
__device__ float g_h[(size_t)NN * HH];
__device__ __align__(16) __half g_uh[(size_t)NN * HH];
__device__ float g_z[(size_t)NN * HH];
__device__ int   g_deg[NN];
__device__ int   g_rowptr[NN + 1];
__device__ int   g_cur[NN];
__device__ int   g_colidx[2 * EE];
__device__ int   g_bsum[128];
__device__ int   g_boff[128];
__device__ float g_colsum[LL * HH];
__device__ float g_colsq[LL * HH];
__device__ float g_pool[GG * HH];
__device__ float g_cnt[GG];
__device__ __align__(16) u16 g_wthi[9 * HH * HH];
__device__ __align__(16) u16 g_wtlo[9 * HH * HH];

// ------------------ PTX helpers ------------------
__device__ __forceinline__ u32 smem_u32(const void* p) {
    u32 a;
    asm("{ .reg .u64 t; cvta.to.shared.u64 t, %1; cvt.u32.u64 %0, t; }" : "=r"(a) : "l"(p));
    return a;
}
__device__ __forceinline__ void ldm4(u32 r[4], u32 addr) {
    asm volatile("ldmatrix.sync.aligned.m8n8.x4.shared.b16 {%0,%1,%2,%3}, [%4];"
                 : "=r"(r[0]), "=r"(r[1]), "=r"(r[2]), "=r"(r[3]) : "r"(addr));
}
__device__ __forceinline__ void mma16816(float* c, const u32 a[4], u32 b0, u32 b1) {
    asm volatile(
        "mma.sync.aligned.m16n8k16.row.col.f32.f16.f16.f32 "
        "{%0,%1,%2,%3}, {%4,%5,%6,%7}, {%8,%9}, {%0,%1,%2,%3};"
        : "+f"(c[0]), "+f"(c[1]), "+f"(c[2]), "+f"(c[3])
        : "r"(a[0]), "r"(a[1]), "r"(a[2]), "r"(a[3]), "r"(b0), "r"(b1));
}
__device__ __forceinline__ u32 packhf2(float x, float y) {
    __half2 t = __floats2half2_rn(x, y);
    return *(u32*)&t;
}

constexpr int SMEM_HM = 100864;
constexpr int F_BIAS = 24576, F_LNG = 24704, F_LNB = 24832, F_SC = 24960, F_SH = 25088;

// ------------------ fused HMMA fp16 2-term GEMM: 512 threads, 4x4 warp grid ------------------
// MODE 0: C = A@W + b                       (A fp32)
// MODE 1: C = A@W + b, column stats         (A fp16 pre-rounded)
// MODE 2: fold BN; A' = relu(A*sc+sh); C = LayerNorm(C + relu(A'@W + b))   (A fp32)
template <int MODE>
__global__ void __launch_bounds__(512, 2) gemm_hmma(
    const void* __restrict__ Ax, const u16* __restrict__ Whi, const u16* __restrict__ Wlo,
    const float* __restrict__ bias, float* __restrict__ C,
    const float* __restrict__ lng, const float* __restrict__ lnb,
    const float* __restrict__ bng, const float* __restrict__ bnb, int layer)
{
    extern __shared__ float sm[];
    const u32 sb = smem_u32(sm);
    const int tid = threadIdx.x;
    const int lane = tid & 31, wid = tid >> 5;
    const int row0 = blockIdx.x * 128;

    if (tid < 128) {
        sm[F_BIAS + tid] = __ldg(bias + tid);
        if (MODE == 2) {
            sm[F_LNG + tid] = __ldg(lng + tid);
            sm[F_LNB + tid] = __ldg(lnb + tid);
            float m = g_colsum[layer * HH + tid] * (1.0f / NN);
            float v = g_colsq[layer * HH + tid] * (1.0f / NN) - m * m;
            float sc = __ldg(bng + tid) * rsqrtf(v + 1e-5f);
            sm[F_SC + tid] = sc;
            sm[F_SH + tid] = __ldg(bnb + tid) - m * sc;
        }
    }
    if (MODE == 2) __syncthreads();

    // ---- single load phase: B (both halves, hi+lo) then A (both halves) ----
#pragma unroll
    for (int i = 0; i < 4; i++) {
        int f = i * 512 + tid;                 // 2048 uint4 per matrix
        int h = f >> 10, r = (f >> 3) & 127, q = f & 7;
        uint4 vh = __ldg((const uint4*)(Whi + (size_t)r * HH + h * 64) + q);
        uint4 vl = __ldg((const uint4*)(Wlo + (size_t)r * HH + h * 64) + q);
        u32 off = (u32)(h * 16384 + r * 128 + ((q ^ (r & 7)) << 4));
        *(uint4*)((char*)sm + 32768 + off) = vh;
        *(uint4*)((char*)sm + 65536 + off) = vl;
    }
    if (MODE == 1) {
        const __half* Af = (const __half*)Ax;
#pragma unroll
        for (int i = 0; i < 8; i++) {
            int f = i * 512 + tid;             // 4096 uint2
            int h = f >> 11, r = (f >> 4) & 127, c4 = f & 15;
            int row = row0 + r;
            uint2 v = make_uint2(0u, 0u);
            if (row < NN) v = __ldg((const uint2*)(Af + (size_t)row * HH + h * 64) + c4);
            u32 off = (u32)(h * 16384 + r * 128 + (((c4 >> 1) ^ (r & 7)) << 4) + (c4 & 1) * 8);
            *(uint2*)((char*)sm + off) = v;
        }
    } else {
        const float* A = (const float*)Ax;
#pragma unroll
        for (int i = 0; i < 8; i++) {
            int f = i * 512 + tid;             // 4096 float4
            int h = f >> 11, r = (f >> 4) & 127, c4 = f & 15;
            int row = row0 + r;
            float4 v = make_float4(0.f, 0.f, 0.f, 0.f);
            if (row < NN) v = __ldg((const float4*)(A + (size_t)row * HH + h * 64) + c4);
            if (MODE == 2) {
                float4 sc = *(float4*)&sm[F_SC + h * 64 + c4 * 4];
                float4 sh = *(float4*)&sm[F_SH + h * 64 + c4 * 4];
                v.x = fmaxf(fmaf(v.x, sc.x, sh.x), 0.f);
                v.y = fmaxf(fmaf(v.y, sc.y, sh.y), 0.f);
                v.z = fmaxf(fmaf(v.z, sc.z, sh.z), 0.f);
                v.w = fmaxf(fmaf(v.w, sc.w, sh.w), 0.f);
            }
            u32 off = (u32)(h * 16384 + r * 128 + (((c4 >> 1) ^ (r & 7)) << 4) + (c4 & 1) * 8);
            *(uint2*)((char*)sm + off) = make_uint2(packhf2(v.x, v.y), packhf2(v.z, v.w));
        }
    }
    __syncthreads();

    // ---- mainloop: 8 k-steps, 4x4 warp grid (each warp 32 rows x 32 cols) ----
    float c[2][4][4];
#pragma unroll
    for (int j = 0; j < 2; j++)
#pragma unroll
        for (int n = 0; n < 4; n++)
#pragma unroll
            for (int q = 0; q < 4; q++) c[j][n][q] = 0.f;

    const int arb = ((wid & 3) << 5) + (lane & 7) + (lane & 8);
    const int cb = (wid >> 2) << 5;
    const int bq = ((lane >> 4) << 3) + (lane & 7);
#pragma unroll
    for (int h = 0; h < 2; h++) {
        const u32 hb = (u32)(h * 16384);
#pragma unroll
        for (int s = 0; s < 4; s++) {
            int ach = 2 * s + (lane >> 4);
            u32 ah[2][4];
#pragma unroll
            for (int j = 0; j < 2; j++) {
                u32 aoff = hb + (u32)((arb + j * 16) * 128 + ((ach ^ (arb & 7)) << 4));
                ldm4(ah[j], sb + aoff);
            }
            int bch = 2 * s + ((lane >> 3) & 1);
#pragma unroll
            for (int n2 = 0; n2 < 2; n2++) {
                int bn = cb + (n2 << 4) + bq;
                u32 boff = hb + (u32)(bn * 128 + ((bch ^ (bn & 7)) << 4));
                u32 bh[4], bl[4];
                ldm4(bh, sb + 32768 + boff);
                ldm4(bl, sb + 65536 + boff);
#pragma unroll
                for (int j = 0; j < 2; j++) {
                    mma16816(c[j][2 * n2],     ah[j], bh[0], bh[1]);
                    mma16816(c[j][2 * n2],     ah[j], bl[0], bl[1]);
                    mma16816(c[j][2 * n2 + 1], ah[j], bh[2], bh[3]);
                    mma16816(c[j][2 * n2 + 1], ah[j], bl[2], bl[3]);
                }
            }
        }
    }
    __syncthreads();

    // ---- stage C + bias into smem [128][132] fp32 ----
    {
        const int r0s = ((wid & 3) << 5) + (lane >> 2);
        const int c0s = ((wid >> 2) << 5) + (lane & 3) * 2;
#pragma unroll
        for (int j = 0; j < 2; j++)
#pragma unroll
            for (int n = 0; n < 4; n++) {
                int col = c0s + n * 8;
                float b0 = sm[F_BIAS + col], b1 = sm[F_BIAS + col + 1];
                *(float2*)&sm[(r0s + j * 16) * 132 + col] =
                    make_float2(c[j][n][0] + b0, c[j][n][1] + b1);
                *(float2*)&sm[(r0s + j * 16 + 8) * 132 + col] =
                    make_float2(c[j][n][2] + b0, c[j][n][3] + b1);
            }
    }
    __syncthreads();

    if (MODE != 2) {
#pragma unroll
        for (int it = 0; it < 2; it++) {
            int r = it * 64 + (tid >> 3);
            int grow = row0 + r;
            if (grow < NN) {
                float* cp = C + (size_t)grow * HH;
#pragma unroll
                for (int j = 0; j < 4; j++) {
                    int c4 = (tid & 7) + j * 8;
                    *(float4*)(cp + c4 * 4) = *(float4*)&sm[r * 132 + c4 * 4];
                }
            }
        }
        if (MODE == 1 && tid < 128) {
            float s = 0.f, sq = 0.f;
            int rmax = NN - row0; if (rmax > 128) rmax = 128;
            for (int r = 0; r < rmax; r++) {
                float v = sm[r * 132 + tid];
                s += v; sq += v * v;
            }
            atomicAdd(&g_colsum[layer * HH + tid], s);
            atomicAdd(&g_colsq[layer * HH + tid], sq);
        }
    } else {
        // coalesced residual + LayerNorm: 8 threads per row, all 512 active
        const int rr8 = tid >> 3;
        const int cq = tid & 7;
#pragma unroll
        for (int it = 0; it < 2; it++) {
            int r = it * 64 + rr8;
            int grow = row0 + r;
            bool valid = grow < NN;
            float* hp = C + (size_t)grow * HH;
            float4 t[4];
            float s = 0.f, sq = 0.f;
#pragma unroll
            for (int j = 0; j < 4; j++) {
                int c4 = cq + j * 8;
                float4 o = *(float4*)&sm[r * 132 + c4 * 4];
                float4 hv = make_float4(0.f, 0.f, 0.f, 0.f);
                if (valid) hv = *(float4*)(hp + c4 * 4);
                t[j].x = hv.x + fmaxf(o.x, 0.f);
                t[j].y = hv.y + fmaxf(o.y, 0.f);
                t[j].z = hv.z + fmaxf(o.z, 0.f);
                t[j].w = hv.w + fmaxf(o.w, 0.f);
                s += t[j].x + t[j].y + t[j].z + t[j].w;
                sq += t[j].x * t[j].x + t[j].y * t[j].y + t[j].z * t[j].z + t[j].w * t[j].w;
            }
#pragma unroll
            for (int m = 1; m < 8; m <<= 1) {
                s  += __shfl_xor_sync(0xFFFFFFFFu, s, m);
                sq += __shfl_xor_sync(0xFFFFFFFFu, sq, m);
            }
            float mean = s * (1.0f / 128.0f);
            float var = sq * (1.0f / 128.0f) - mean * mean;
            float rf = rsqrtf(var + 1e-5f);
            if (valid) {
#pragma unroll
                for (int j = 0; j < 4; j++) {
                    int c4 = cq + j * 8;
                    float4 lg = *(float4*)&sm[F_LNG + c4 * 4];
                    float4 lb = *(float4*)&sm[F_LNB + c4 * 4];
                    float4 w;
                    w.x = (t[j].x - mean) * rf * lg.x + lb.x;
                    w.y = (t[j].y - mean) * rf * lg.y + lb.y;
                    w.z = (t[j].z - mean) * rf * lg.z + lb.z;
                    w.w = (t[j].w - mean) * rf * lg.w + lb.w;
                    *(float4*)(hp + c4 * 4) = w;
                }
            }
        }
    }
}

// ------------------ weight transpose + fp16 split ------------------
__global__ void transposek(const float* __restrict__ W0, const float* __restrict__ W1,
                           const float* __restrict__ W2) {
    int i = blockIdx.x * 256 + threadIdx.x;
    if (i >= 9 * HH * HH) return;
    int s = i >> 14, r = i & 16383;
    int n = r >> 7, k = r & 127;
    const float* src = (s == 0) ? W0 : (s < 5 ? W1 + (s - 1) * HH * HH : W2 + (s - 5) * HH * HH);
    float x = __ldg(src + k * HH + n);
    __half hb = __float2half_rn(x);
    float hi = __half2float(hb);
    __half lb = __float2half_rn(x - hi);
    g_wthi[i] = *(u16*)&hb;
    g_wtlo[i] = *(u16*)&lb;
}

// ------------------ graph preprocessing ------------------
__global__ void degk(const int* __restrict__ ei) {
    int e = blockIdx.x * blockDim.x + threadIdx.x;
    if (e >= EE) return;
    int r = ei[e], c = ei[EE + e];
    if (r != c) { atomicAdd(&g_deg[r], 1); atomicAdd(&g_deg[c], 1); }
}

__global__ void scan1k() {
    int b = blockIdx.x, t = threadIdx.x;
    int i = b * 1024 + t;
    int lane = t & 31, wid = t >> 5;
    __shared__ int wsumS[32];
    int v = (i < NN) ? g_deg[i] : 0;
    int x = v;
#pragma unroll
    for (int d = 1; d < 32; d <<= 1) {
        int y = __shfl_up_sync(0xFFFFFFFFu, x, d);
        if (lane >= d) x += y;
    }
    if (lane == 31) wsumS[wid] = x;
    __syncthreads();
    if (wid == 0) {
        int w = wsumS[lane];
#pragma unroll
        for (int d = 1; d < 32; d <<= 1) {
            int y = __shfl_up_sync(0xFFFFFFFFu, w, d);
            if (lane >= d) w += y;
        }
        wsumS[lane] = w;
    }
    __syncthreads();
    int excl = (wid > 0 ? wsumS[wid - 1] : 0) + x - v;
    if (i < NN) g_rowptr[i] = excl;
    if (t == 1023) g_bsum[b] = excl + v;
}

__global__ void scan2k(int nblk) {
    int t = threadIdx.x;
    __shared__ int s[128];
    int v = (t < nblk) ? g_bsum[t] : 0;
    s[t] = v;
    __syncthreads();
    for (int d = 1; d < 128; d <<= 1) {
        int y = 0;
        if (t >= d) y = s[t - d];
        __syncthreads();
        if (t >= d) s[t] += y;
        __syncthreads();
    }
    g_boff[t] = s[t] - v;
    if (t == 127) g_rowptr[NN] = s[127];
}

__global__ void scan3k() {
    int i = blockIdx.x * 1024 + threadIdx.x;
    if (i < NN) {
        int r = g_rowptr[i] + g_boff[blockIdx.x];
        g_rowptr[i] = r;
        g_cur[i] = r;
    }
}

__global__ void fillk(const int* __restrict__ ei) {
    int e = blockIdx.x * blockDim.x + threadIdx.x;
    if (e >= EE) return;
    int r = ei[e], c = ei[EE + e];
    if (r != c) {
        int p = atomicAdd(&g_cur[r], 1); g_colidx[p] = c;
        int q = atomicAdd(&g_cur[c], 1); g_colidx[q] = r;
    }
}

// ------------------ GIN aggregation: warp/node, MLP-8, fp16 output ------------------
__global__ void aggk(const float* __restrict__ h, __half* __restrict__ uh,
                     const float* __restrict__ eps_l, int layer) {
    int w = (blockIdx.x * blockDim.x + threadIdx.x) >> 5;
    if (w >= NN) return;
    int lane = threadIdx.x & 31;
    float e1 = 1.0f + __ldg(eps_l + layer);
    const float4* hp = (const float4*)h;
    float4 a = __ldg(hp + (size_t)w * 32 + lane);
    float4 acc = make_float4(a.x * e1, a.y * e1, a.z * e1, a.w * e1);
    int beg = g_rowptr[w], end = g_rowptr[w + 1];
    int e = beg;
    for (; e + 8 <= end; e += 8) {
        int idx[8];
#pragma unroll
        for (int t = 0; t < 8; t++) idx[t] = g_colidx[e + t];
        float4 v[8];
#pragma unroll
        for (int t = 0; t < 8; t++) v[t] = __ldg(hp + (size_t)idx[t] * 32 + lane);
#pragma unroll
        for (int t = 0; t < 8; t++) {
            acc.x += v[t].x; acc.y += v[t].y; acc.z += v[t].z; acc.w += v[t].w;
        }
    }
    if (e + 4 <= end) {
        int idx[4];
#pragma unroll
        for (int t = 0; t < 4; t++) idx[t] = g_colidx[e + t];
        float4 v[4];
#pragma unroll
        for (int t = 0; t < 4; t++) v[t] = __ldg(hp + (size_t)idx[t] * 32 + lane);
#pragma unroll
        for (int t = 0; t < 4; t++) {
            acc.x += v[t].x; acc.y += v[t].y; acc.z += v[t].z; acc.w += v[t].w;
        }
        e += 4;
    }
    for (; e < end; e++) {
        int nb = g_colidx[e];
        float4 v = __ldg(hp + (size_t)nb * 32 + lane);
        acc.x += v.x; acc.y += v.y; acc.z += v.z; acc.w += v.w;
    }
    ((uint2*)uh)[(size_t)w * 32 + lane] =
        make_uint2(packhf2(acc.x, acc.y), packhf2(acc.z, acc.w));
}

// ------------------ pooling (batch is sorted) ------------------
__global__ void poolk(const float* __restrict__ h, const int* __restrict__ batch) {
    int f = threadIdx.x;
    int chunk = (NN + gridDim.x - 1) / gridDim.x;
    int s = blockIdx.x * chunk;
    int e = s + chunk; if (e > NN) e = NN;
    if (s >= e) return;
    int g = __ldg(batch + s);
    float acc = 0.f, cnt = 0.f;
    for (int n = s; n < e; n++) {
        int bg = __ldg(batch + n);
        if (bg != g) {
            atomicAdd(&g_pool[g * HH + f], acc);
            if (f == 0) atomicAdd(&g_cnt[g], cnt);
            acc = 0.f; cnt = 0.f; g = bg;
        }
        acc += h[(size_t)n * HH + f];
        cnt += 1.f;
    }
    atomicAdd(&g_pool[g * HH + f], acc);
    if (f == 0) atomicAdd(&g_cnt[g], cnt);
}

__global__ void finalk(float* __restrict__ out) {
    int i = blockIdx.x * blockDim.x + threadIdx.x;
    if (i < GG * HH) {
        float c = g_cnt[i >> 7];
        out[i] = g_pool[i] / fmaxf(c, 1.0f);
    }
}

// ------------------ host launcher ------------------
extern "C" void kernel_launch(void* const* d_in, const int* in_sizes, int n_in,
                              void* d_out, int out_size) {
    const float* x     = (const float*)d_in[0];
    const float* W0    = (const float*)d_in[1];
    const float* b0    = (const float*)d_in[2];
    const float* eps_l = (const float*)d_in[3];
    const float* W1    = (const float*)d_in[4];
    const float* b1    = (const float*)d_in[5];
    const float* bng   = (const float*)d_in[6];
    const float* bnb   = (const float*)d_in[7];
    const float* W2    = (const float*)d_in[8];
    const float* b2    = (const float*)d_in[9];
    const float* lng   = (const float*)d_in[10];
    const float* lnb   = (const float*)d_in[11];
    const int*   ei    = (const int*)d_in[12];
    const int*   batch = (const int*)d_in[13];
    float* out = (float*)d_out;

    cudaFuncSetAttribute((const void*)gemm_hmma<0>, cudaFuncAttributeMaxDynamicSharedMemorySize, SMEM_HM);
    cudaFuncSetAttribute((const void*)gemm_hmma<1>, cudaFuncAttributeMaxDynamicSharedMemorySize, SMEM_HM);
    cudaFuncSetAttribute((const void*)gemm_hmma<2>, cudaFuncAttributeMaxDynamicSharedMemorySize, SMEM_HM);

    float *ph, *pz, *pcs, *pcq, *ppool, *pcnt;
    __half* puh;
    int *pdeg;
    u16 *pwh, *pwl;
    cudaGetSymbolAddress((void**)&ph, g_h);
    cudaGetSymbolAddress((void**)&puh, g_uh);
    cudaGetSymbolAddress((void**)&pz, g_z);
    cudaGetSymbolAddress((void**)&pcs, g_colsum);
    cudaGetSymbolAddress((void**)&pcq, g_colsq);
    cudaGetSymbolAddress((void**)&ppool, g_pool);
    cudaGetSymbolAddress((void**)&pcnt, g_cnt);
    cudaGetSymbolAddress((void**)&pdeg, g_deg);
    cudaGetSymbolAddress((void**)&pwh, g_wthi);
    cudaGetSymbolAddress((void**)&pwl, g_wtlo);

    const int NB = (NN + 1023) / 1024;   // 98
    const int GB = (NN + 127) / 128;     // 782

    cudaStream_t s2;
    cudaStreamCreateWithFlags(&s2, cudaStreamNonBlocking);
    cudaEvent_t evF, evJ;
    cudaEventCreateWithFlags(&evF, cudaEventDisableTiming);
    cudaEventCreateWithFlags(&evJ, cudaEventDisableTiming);

    cudaMemsetAsync(pdeg, 0, NN * sizeof(int));
    cudaMemsetAsync(pcs, 0, LL * HH * sizeof(float));
    cudaMemsetAsync(pcq, 0, LL * HH * sizeof(float));
    cudaMemsetAsync(ppool, 0, GG * HH * sizeof(float));
    cudaMemsetAsync(pcnt, 0, GG * sizeof(float));

    cudaEventRecord(evF, 0);
    cudaStreamWaitEvent(s2, evF, 0);

    // main stream: weights -> encoder GEMM; side stream: CSR build (independent)
    transposek<<<(9 * HH * HH + 255) / 256, 256>>>(W0, W1, W2);
    degk<<<(EE + 255) / 256, 256, 0, s2>>>(ei);
    scan1k<<<NB, 1024, 0, s2>>>();
    gemm_hmma<0><<<GB, 512, SMEM_HM>>>(x, pwh, pwl, b0, ph,
                                       nullptr, nullptr, nullptr, nullptr, 0);  // ncu slot
    scan2k<<<1, 128, 0, s2>>>(NB);
    scan3k<<<NB, 1024, 0, s2>>>();
    fillk<<<(EE + 255) / 256, 256, 0, s2>>>(ei);
    cudaEventRecord(evJ, s2);
    cudaStreamWaitEvent(0, evJ, 0);

    for (int i = 0; i < LL; i++) {
        aggk<<<(NN * 32 + 255) / 256, 256>>>(ph, puh, eps_l, i);
        gemm_hmma<1><<<GB, 512, SMEM_HM>>>(puh, pwh + (1 + i) * HH * HH, pwl + (1 + i) * HH * HH,
                                           b1 + i * HH, pz, nullptr, nullptr, nullptr, nullptr, i);
        gemm_hmma<2><<<GB, 512, SMEM_HM>>>(pz, pwh + (5 + i) * HH * HH, pwl + (5 + i) * HH * HH,
                                           b2 + i * HH, ph, lng + i * HH, lnb + i * HH,
                                           bng + i * HH, bnb + i * HH, i);
    }

    poolk<<<1000, 128>>>(ph, batch);
    finalk<<<(GG * HH + 255) / 256, 256>>>(out);

    cudaStreamDestroy(s2);
    cudaEventDestroy(evF);
    cudaEventDestroy(evJ);
}

// round 17
// speedup vs baseline: 1.0413x; 1.0413x over previous
#include <cuda_runtime.h>
#include <cuda_fp16.h>

#define NN 100000
#define EE 800000
#define HH 128
#define GG 64
#define LL 4

typedef unsigned int u32;
typedef unsigned short u16;

// ------------------ static device scratch ------------------
__device__ float g_h[(size_t)NN * HH];
__device__ __align__(16) __half g_uh[(size_t)NN * HH];   // u in fp16
__device__ __align__(16) __half g_zh[(size_t)NN * HH];   // z in fp16
__device__ int   g_deg[NN];
__device__ int   g_rowptr[NN + 1];
__device__ int   g_cur[NN];
__device__ int   g_colidx[2 * EE];
__device__ int   g_bsum[128];
__device__ int   g_boff[128];
__device__ float g_colsum[LL * HH];
__device__ float g_colsq[LL * HH];
__device__ float g_pool[GG * HH];
__device__ float g_cnt[GG];
__device__ __align__(16) u16 g_wthi[9 * HH * HH];
__device__ __align__(16) u16 g_wtlo[9 * HH * HH];

// ------------------ PTX helpers ------------------
__device__ __forceinline__ u32 smem_u32(const void* p) {
    u32 a;
    asm("{ .reg .u64 t; cvta.to.shared.u64 t, %1; cvt.u32.u64 %0, t; }" : "=r"(a) : "l"(p));
    return a;
}
__device__ __forceinline__ void ldm4(u32 r[4], u32 addr) {
    asm volatile("ldmatrix.sync.aligned.m8n8.x4.shared.b16 {%0,%1,%2,%3}, [%4];"
                 : "=r"(r[0]), "=r"(r[1]), "=r"(r[2]), "=r"(r[3]) : "r"(addr));
}
__device__ __forceinline__ void mma16816(float* c, const u32 a[4], u32 b0, u32 b1) {
    asm volatile(
        "mma.sync.aligned.m16n8k16.row.col.f32.f16.f16.f32 "
        "{%0,%1,%2,%3}, {%4,%5,%6,%7}, {%8,%9}, {%0,%1,%2,%3};"
        : "+f"(c[0]), "+f"(c[1]), "+f"(c[2]), "+f"(c[3])
        : "r"(a[0]), "r"(a[1]), "r"(a[2]), "r"(a[3]), "r"(b0), "r"(b1));
}
__device__ __forceinline__ u32 packhf2(float x, float y) {
    __half2 t = __floats2half2_rn(x, y);
    return *(u32*)&t;
}

constexpr int SMEM_HM = 100864;
constexpr int F_BIAS = 24576, F_LNG = 24704, F_LNB = 24832, F_SC = 24960, F_SH = 25088;

// ------------------ fused HMMA fp16 2-term GEMM: single-phase full-K, 256 thr ------------------
// MODE 0: h = x@W + b                        (A fp32 in, C fp32 out)
// MODE 1: zh = x@W + b (fp16 out), fp32 column stats   (A fp16 in)
// MODE 2: fold BN; A' = relu(zh*sc+sh); h = LayerNorm(h + relu(A'@W + b))  (A fp16 in, C fp32 in/out)
template <int MODE>
__global__ void __launch_bounds__(256, 2) gemm_hmma(
    const void* __restrict__ Ax, const u16* __restrict__ Whi, const u16* __restrict__ Wlo,
    const float* __restrict__ bias, void* __restrict__ Cx,
    const float* __restrict__ lng, const float* __restrict__ lnb,
    const float* __restrict__ bng, const float* __restrict__ bnb, int layer)
{
    extern __shared__ float sm[];
    const u32 sb = smem_u32(sm);
    const int tid = threadIdx.x;
    const int lane = tid & 31, wid = tid >> 5;
    const int row0 = blockIdx.x * 128;

    if (tid < 128) {
        sm[F_BIAS + tid] = __ldg(bias + tid);
        if (MODE == 2) {
            sm[F_LNG + tid] = __ldg(lng + tid);
            sm[F_LNB + tid] = __ldg(lnb + tid);
            float m = g_colsum[layer * HH + tid] * (1.0f / NN);
            float v = g_colsq[layer * HH + tid] * (1.0f / NN) - m * m;
            float sc = __ldg(bng + tid) * rsqrtf(v + 1e-5f);
            sm[F_SC + tid] = sc;
            sm[F_SH + tid] = __ldg(bnb + tid) - m * sc;
        }
    }
    if (MODE == 2) __syncthreads();

    // ---- single load phase: B (both halves, hi+lo) then A (both halves) ----
#pragma unroll
    for (int i = 0; i < 8; i++) {
        int f = i * 256 + tid;
        int h = f >> 10, r = (f >> 3) & 127, q = f & 7;
        uint4 vh = __ldg((const uint4*)(Whi + (size_t)r * HH + h * 64) + q);
        uint4 vl = __ldg((const uint4*)(Wlo + (size_t)r * HH + h * 64) + q);
        u32 off = (u32)(h * 16384 + r * 128 + ((q ^ (r & 7)) << 4));
        *(uint4*)((char*)sm + 32768 + off) = vh;
        *(uint4*)((char*)sm + 65536 + off) = vl;
    }
    if (MODE == 0) {
        const float* A = (const float*)Ax;
#pragma unroll
        for (int i = 0; i < 16; i++) {
            int f = i * 256 + tid;
            int h = f >> 11, r = (f >> 4) & 127, c4 = f & 15;
            int row = row0 + r;
            float4 v = make_float4(0.f, 0.f, 0.f, 0.f);
            if (row < NN) v = __ldg((const float4*)(A + (size_t)row * HH + h * 64) + c4);
            u32 off = (u32)(h * 16384 + r * 128 + (((c4 >> 1) ^ (r & 7)) << 4) + (c4 & 1) * 8);
            *(uint2*)((char*)sm + off) = make_uint2(packhf2(v.x, v.y), packhf2(v.z, v.w));
        }
    } else if (MODE == 1) {
        const __half* Af = (const __half*)Ax;
#pragma unroll
        for (int i = 0; i < 16; i++) {
            int f = i * 256 + tid;
            int h = f >> 11, r = (f >> 4) & 127, c4 = f & 15;
            int row = row0 + r;
            uint2 v = make_uint2(0u, 0u);
            if (row < NN) v = __ldg((const uint2*)(Af + (size_t)row * HH + h * 64) + c4);
            u32 off = (u32)(h * 16384 + r * 128 + (((c4 >> 1) ^ (r & 7)) << 4) + (c4 & 1) * 8);
            *(uint2*)((char*)sm + off) = v;
        }
    } else {
        const __half* Af = (const __half*)Ax;   // fp16 z
#pragma unroll
        for (int i = 0; i < 16; i++) {
            int f = i * 256 + tid;
            int h = f >> 11, r = (f >> 4) & 127, c4 = f & 15;
            int row = row0 + r;
            uint2 raw = make_uint2(0u, 0u);
            if (row < NN) raw = __ldg((const uint2*)(Af + (size_t)row * HH + h * 64) + c4);
            float2 f0 = __half22float2(*(__half2*)&raw.x);
            float2 f1 = __half22float2(*(__half2*)&raw.y);
            float4 sc = *(float4*)&sm[F_SC + h * 64 + c4 * 4];
            float4 sh = *(float4*)&sm[F_SH + h * 64 + c4 * 4];
            float vx = fmaxf(fmaf(f0.x, sc.x, sh.x), 0.f);
            float vy = fmaxf(fmaf(f0.y, sc.y, sh.y), 0.f);
            float vz = fmaxf(fmaf(f1.x, sc.z, sh.z), 0.f);
            float vw = fmaxf(fmaf(f1.y, sc.w, sh.w), 0.f);
            u32 off = (u32)(h * 16384 + r * 128 + (((c4 >> 1) ^ (r & 7)) << 4) + (c4 & 1) * 8);
            *(uint2*)((char*)sm + off) = make_uint2(packhf2(vx, vy), packhf2(vz, vw));
        }
    }
    __syncthreads();

    // ---- uninterrupted mainloop: 8 k-steps, 4x2 warp grid ----
    float c[2][8][4];
#pragma unroll
    for (int j = 0; j < 2; j++)
#pragma unroll
        for (int n = 0; n < 8; n++)
#pragma unroll
            for (int q = 0; q < 4; q++) c[j][n][q] = 0.f;

    const int arb = ((wid & 3) << 5) + (lane & 7) + (lane & 8);
    const int cb = (wid >> 2) << 6;
    const int bq = ((lane >> 4) << 3) + (lane & 7);
#pragma unroll
    for (int h = 0; h < 2; h++) {
        const u32 hb = (u32)(h * 16384);
#pragma unroll
        for (int s = 0; s < 4; s++) {
            int ach = 2 * s + (lane >> 4);
            u32 ah[2][4];
#pragma unroll
            for (int j = 0; j < 2; j++) {
                u32 aoff = hb + (u32)((arb + j * 16) * 128 + ((ach ^ (arb & 7)) << 4));
                ldm4(ah[j], sb + aoff);
            }
            int bch = 2 * s + ((lane >> 3) & 1);
#pragma unroll
            for (int n2 = 0; n2 < 4; n2++) {
                int bn = cb + (n2 << 4) + bq;
                u32 boff = hb + (u32)(bn * 128 + ((bch ^ (bn & 7)) << 4));
                u32 bh[4], bl[4];
                ldm4(bh, sb + 32768 + boff);
                ldm4(bl, sb + 65536 + boff);
#pragma unroll
                for (int j = 0; j < 2; j++) {
                    mma16816(c[j][2 * n2],     ah[j], bh[0], bh[1]);
                    mma16816(c[j][2 * n2],     ah[j], bl[0], bl[1]);
                    mma16816(c[j][2 * n2 + 1], ah[j], bh[2], bh[3]);
                    mma16816(c[j][2 * n2 + 1], ah[j], bl[2], bl[3]);
                }
            }
        }
    }
    __syncthreads();

    // ---- stage C + bias into smem [128][132] fp32 ----
    {
        const int r0s = ((wid & 3) << 5) + (lane >> 2);
        const int c0s = ((wid >> 2) << 6) + (lane & 3) * 2;
#pragma unroll
        for (int j = 0; j < 2; j++)
#pragma unroll
            for (int n = 0; n < 8; n++) {
                int col = c0s + n * 8;
                float b0 = sm[F_BIAS + col], b1 = sm[F_BIAS + col + 1];
                *(float2*)&sm[(r0s + j * 16) * 132 + col] =
                    make_float2(c[j][n][0] + b0, c[j][n][1] + b1);
                *(float2*)&sm[(r0s + j * 16 + 8) * 132 + col] =
                    make_float2(c[j][n][2] + b0, c[j][n][3] + b1);
            }
    }
    __syncthreads();

    if (MODE == 0) {
        float* C = (float*)Cx;
#pragma unroll
        for (int it = 0; it < 4; it++) {
            int r = it * 32 + (tid >> 3);
            int grow = row0 + r;
            if (grow < NN) {
                float* cp = C + (size_t)grow * HH;
#pragma unroll
                for (int j = 0; j < 4; j++) {
                    int c4 = (tid & 7) + j * 8;
                    *(float4*)(cp + c4 * 4) = *(float4*)&sm[r * 132 + c4 * 4];
                }
            }
        }
    } else if (MODE == 1) {
        __half* C = (__half*)Cx;
#pragma unroll
        for (int it = 0; it < 4; it++) {
            int r = it * 32 + (tid >> 3);
            int grow = row0 + r;
            if (grow < NN) {
                __half* cp = C + (size_t)grow * HH;
#pragma unroll
                for (int j = 0; j < 4; j++) {
                    int c4 = (tid & 7) + j * 8;
                    float4 v = *(float4*)&sm[r * 132 + c4 * 4];
                    *(uint2*)(cp + c4 * 4) = make_uint2(packhf2(v.x, v.y), packhf2(v.z, v.w));
                }
            }
        }
        if (tid < 128) {
            float s = 0.f, sq = 0.f;
            int rmax = NN - row0; if (rmax > 128) rmax = 128;
            for (int r = 0; r < rmax; r++) {
                float v = sm[r * 132 + tid];
                s += v; sq += v * v;
            }
            atomicAdd(&g_colsum[layer * HH + tid], s);
            atomicAdd(&g_colsq[layer * HH + tid], sq);
        }
    } else {
        // coalesced residual + LayerNorm: 8 threads per row, all 256 active
        float* C = (float*)Cx;
        const int rr8 = tid >> 3;
        const int cq = tid & 7;
#pragma unroll
        for (int it = 0; it < 4; it++) {
            int r = it * 32 + rr8;
            int grow = row0 + r;
            bool valid = grow < NN;
            float* hp = C + (size_t)grow * HH;
            float4 t[4];
            float s = 0.f, sq = 0.f;
#pragma unroll
            for (int j = 0; j < 4; j++) {
                int c4 = cq + j * 8;
                float4 o = *(float4*)&sm[r * 132 + c4 * 4];
                float4 hv = make_float4(0.f, 0.f, 0.f, 0.f);
                if (valid) hv = *(float4*)(hp + c4 * 4);
                t[j].x = hv.x + fmaxf(o.x, 0.f);
                t[j].y = hv.y + fmaxf(o.y, 0.f);
                t[j].z = hv.z + fmaxf(o.z, 0.f);
                t[j].w = hv.w + fmaxf(o.w, 0.f);
                s += t[j].x + t[j].y + t[j].z + t[j].w;
                sq += t[j].x * t[j].x + t[j].y * t[j].y + t[j].z * t[j].z + t[j].w * t[j].w;
            }
#pragma unroll
            for (int m = 1; m < 8; m <<= 1) {
                s  += __shfl_xor_sync(0xFFFFFFFFu, s, m);
                sq += __shfl_xor_sync(0xFFFFFFFFu, sq, m);
            }
            float mean = s * (1.0f / 128.0f);
            float var = sq * (1.0f / 128.0f) - mean * mean;
            float rf = rsqrtf(var + 1e-5f);
            if (valid) {
#pragma unroll
                for (int j = 0; j < 4; j++) {
                    int c4 = cq + j * 8;
                    float4 lg = *(float4*)&sm[F_LNG + c4 * 4];
                    float4 lb = *(float4*)&sm[F_LNB + c4 * 4];
                    float4 w;
                    w.x = (t[j].x - mean) * rf * lg.x + lb.x;
                    w.y = (t[j].y - mean) * rf * lg.y + lb.y;
                    w.z = (t[j].z - mean) * rf * lg.z + lb.z;
                    w.w = (t[j].w - mean) * rf * lg.w + lb.w;
                    *(float4*)(hp + c4 * 4) = w;
                }
            }
        }
    }
}

// ------------------ weight transpose + fp16 split ------------------
__global__ void transposek(const float* __restrict__ W0, const float* __restrict__ W1,
                           const float* __restrict__ W2) {
    int i = blockIdx.x * 256 + threadIdx.x;
    if (i >= 9 * HH * HH) return;
    int s = i >> 14, r = i & 16383;
    int n = r >> 7, k = r & 127;
    const float* src = (s == 0) ? W0 : (s < 5 ? W1 + (s - 1) * HH * HH : W2 + (s - 5) * HH * HH);
    float x = __ldg(src + k * HH + n);
    __half hb = __float2half_rn(x);
    float hi = __half2float(hb);
    __half lb = __float2half_rn(x - hi);
    g_wthi[i] = *(u16*)&hb;
    g_wtlo[i] = *(u16*)&lb;
}

// ------------------ graph preprocessing ------------------
__global__ void degk(const int* __restrict__ ei) {
    int e = blockIdx.x * blockDim.x + threadIdx.x;
    if (e >= EE) return;
    int r = ei[e], c = ei[EE + e];
    if (r != c) { atomicAdd(&g_deg[r], 1); atomicAdd(&g_deg[c], 1); }
}

__global__ void scan1k() {
    int b = blockIdx.x, t = threadIdx.x;
    int i = b * 1024 + t;
    int lane = t & 31, wid = t >> 5;
    __shared__ int wsumS[32];
    int v = (i < NN) ? g_deg[i] : 0;
    int x = v;
#pragma unroll
    for (int d = 1; d < 32; d <<= 1) {
        int y = __shfl_up_sync(0xFFFFFFFFu, x, d);
        if (lane >= d) x += y;
    }
    if (lane == 31) wsumS[wid] = x;
    __syncthreads();
    if (wid == 0) {
        int w = wsumS[lane];
#pragma unroll
        for (int d = 1; d < 32; d <<= 1) {
            int y = __shfl_up_sync(0xFFFFFFFFu, w, d);
            if (lane >= d) w += y;
        }
        wsumS[lane] = w;
    }
    __syncthreads();
    int excl = (wid > 0 ? wsumS[wid - 1] : 0) + x - v;
    if (i < NN) g_rowptr[i] = excl;
    if (t == 1023) g_bsum[b] = excl + v;
}

__global__ void scan2k(int nblk) {
    int t = threadIdx.x;
    __shared__ int s[128];
    int v = (t < nblk) ? g_bsum[t] : 0;
    s[t] = v;
    __syncthreads();
    for (int d = 1; d < 128; d <<= 1) {
        int y = 0;
        if (t >= d) y = s[t - d];
        __syncthreads();
        if (t >= d) s[t] += y;
        __syncthreads();
    }
    g_boff[t] = s[t] - v;
    if (t == 127) g_rowptr[NN] = s[127];
}

__global__ void scan3k() {
    int i = blockIdx.x * 1024 + threadIdx.x;
    if (i < NN) {
        int r = g_rowptr[i] + g_boff[blockIdx.x];
        g_rowptr[i] = r;
        g_cur[i] = r;
    }
}

__global__ void fillk(const int* __restrict__ ei) {
    int e = blockIdx.x * blockDim.x + threadIdx.x;
    if (e >= EE) return;
    int r = ei[e], c = ei[EE + e];
    if (r != c) {
        int p = atomicAdd(&g_cur[r], 1); g_colidx[p] = c;
        int q = atomicAdd(&g_cur[c], 1); g_colidx[q] = r;
    }
}

// ------------------ GIN aggregation: warp/node, MLP-8, fp16 output ------------------
__global__ void aggk(const float* __restrict__ h, __half* __restrict__ uh,
                     const float* __restrict__ eps_l, int layer) {
    int w = (blockIdx.x * blockDim.x + threadIdx.x) >> 5;
    if (w >= NN) return;
    int lane = threadIdx.x & 31;
    float e1 = 1.0f + __ldg(eps_l + layer);
    const float4* hp = (const float4*)h;
    float4 a = __ldg(hp + (size_t)w * 32 + lane);
    float4 acc = make_float4(a.x * e1, a.y * e1, a.z * e1, a.w * e1);
    int beg = g_rowptr[w], end = g_rowptr[w + 1];
    int e = beg;
    for (; e + 8 <= end; e += 8) {
        int idx[8];
#pragma unroll
        for (int t = 0; t < 8; t++) idx[t] = g_colidx[e + t];
        float4 v[8];
#pragma unroll
        for (int t = 0; t < 8; t++) v[t] = __ldg(hp + (size_t)idx[t] * 32 + lane);
#pragma unroll
        for (int t = 0; t < 8; t++) {
            acc.x += v[t].x; acc.y += v[t].y; acc.z += v[t].z; acc.w += v[t].w;
        }
    }
    if (e + 4 <= end) {
        int idx[4];
#pragma unroll
        for (int t = 0; t < 4; t++) idx[t] = g_colidx[e + t];
        float4 v[4];
#pragma unroll
        for (int t = 0; t < 4; t++) v[t] = __ldg(hp + (size_t)idx[t] * 32 + lane);
#pragma unroll
        for (int t = 0; t < 4; t++) {
            acc.x += v[t].x; acc.y += v[t].y; acc.z += v[t].z; acc.w += v[t].w;
        }
        e += 4;
    }
    for (; e < end; e++) {
        int nb = g_colidx[e];
        float4 v = __ldg(hp + (size_t)nb * 32 + lane);
        acc.x += v.x; acc.y += v.y; acc.z += v.z; acc.w += v.w;
    }
    ((uint2*)uh)[(size_t)w * 32 + lane] =
        make_uint2(packhf2(acc.x, acc.y), packhf2(acc.z, acc.w));
}

// ------------------ pooling (batch is sorted) ------------------
__global__ void poolk(const float* __restrict__ h, const int* __restrict__ batch) {
    int f = threadIdx.x;
    int chunk = (NN + gridDim.x - 1) / gridDim.x;
    int s = blockIdx.x * chunk;
    int e = s + chunk; if (e > NN) e = NN;
    if (s >= e) return;
    int g = __ldg(batch + s);
    float acc = 0.f, cnt = 0.f;
    for (int n = s; n < e; n++) {
        int bg = __ldg(batch + n);
        if (bg != g) {
            atomicAdd(&g_pool[g * HH + f], acc);
            if (f == 0) atomicAdd(&g_cnt[g], cnt);
            acc = 0.f; cnt = 0.f; g = bg;
        }
        acc += h[(size_t)n * HH + f];
        cnt += 1.f;
    }
    atomicAdd(&g_pool[g * HH + f], acc);
    if (f == 0) atomicAdd(&g_cnt[g], cnt);
}

__global__ void finalk(float* __restrict__ out) {
    int i = blockIdx.x * blockDim.x + threadIdx.x;
    if (i < GG * HH) {
        float c = g_cnt[i >> 7];
        out[i] = g_pool[i] / fmaxf(c, 1.0f);
    }
}

// ------------------ host launcher ------------------
extern "C" void kernel_launch(void* const* d_in, const int* in_sizes, int n_in,
                              void* d_out, int out_size) {
    const float* x     = (const float*)d_in[0];
    const float* W0    = (const float*)d_in[1];
    const float* b0    = (const float*)d_in[2];
    const float* eps_l = (const float*)d_in[3];
    const float* W1    = (const float*)d_in[4];
    const float* b1    = (const float*)d_in[5];
    const float* bng   = (const float*)d_in[6];
    const float* bnb   = (const float*)d_in[7];
    const float* W2    = (const float*)d_in[8];
    const float* b2    = (const float*)d_in[9];
    const float* lng   = (const float*)d_in[10];
    const float* lnb   = (const float*)d_in[11];
    const int*   ei    = (const int*)d_in[12];
    const int*   batch = (const int*)d_in[13];
    float* out = (float*)d_out;

    cudaFuncSetAttribute((const void*)gemm_hmma<0>, cudaFuncAttributeMaxDynamicSharedMemorySize, SMEM_HM);
    cudaFuncSetAttribute((const void*)gemm_hmma<1>, cudaFuncAttributeMaxDynamicSharedMemorySize, SMEM_HM);
    cudaFuncSetAttribute((const void*)gemm_hmma<2>, cudaFuncAttributeMaxDynamicSharedMemorySize, SMEM_HM);

    float *ph, *pcs, *pcq, *ppool, *pcnt;
    __half *puh, *pzh;
    int *pdeg;
    u16 *pwh, *pwl;
    cudaGetSymbolAddress((void**)&ph, g_h);
    cudaGetSymbolAddress((void**)&puh, g_uh);
    cudaGetSymbolAddress((void**)&pzh, g_zh);
    cudaGetSymbolAddress((void**)&pcs, g_colsum);
    cudaGetSymbolAddress((void**)&pcq, g_colsq);
    cudaGetSymbolAddress((void**)&ppool, g_pool);
    cudaGetSymbolAddress((void**)&pcnt, g_cnt);
    cudaGetSymbolAddress((void**)&pdeg, g_deg);
    cudaGetSymbolAddress((void**)&pwh, g_wthi);
    cudaGetSymbolAddress((void**)&pwl, g_wtlo);

    const int NB = (NN + 1023) / 1024;   // 98
    const int GB = (NN + 127) / 128;     // 782

    cudaStream_t s2;
    cudaStreamCreateWithFlags(&s2, cudaStreamNonBlocking);
    cudaEvent_t evF, evJ;
    cudaEventCreateWithFlags(&evF, cudaEventDisableTiming);
    cudaEventCreateWithFlags(&evJ, cudaEventDisableTiming);

    cudaMemsetAsync(pdeg, 0, NN * sizeof(int));
    cudaMemsetAsync(pcs, 0, LL * HH * sizeof(float));
    cudaMemsetAsync(pcq, 0, LL * HH * sizeof(float));
    cudaMemsetAsync(ppool, 0, GG * HH * sizeof(float));
    cudaMemsetAsync(pcnt, 0, GG * sizeof(float));

    cudaEventRecord(evF, 0);
    cudaStreamWaitEvent(s2, evF, 0);

    // main stream: weights -> encoder GEMM; side stream: CSR build (independent)
    transposek<<<(9 * HH * HH + 255) / 256, 256>>>(W0, W1, W2);
    degk<<<(EE + 255) / 256, 256, 0, s2>>>(ei);
    scan1k<<<NB, 1024, 0, s2>>>();
    gemm_hmma<0><<<GB, 256, SMEM_HM>>>(x, pwh, pwl, b0, ph,
                                       nullptr, nullptr, nullptr, nullptr, 0);  // ncu slot
    scan2k<<<1, 128, 0, s2>>>(NB);
    scan3k<<<NB, 1024, 0, s2>>>();
    fillk<<<(EE + 255) / 256, 256, 0, s2>>>(ei);
    cudaEventRecord(evJ, s2);
    cudaStreamWaitEvent(0, evJ, 0);

    for (int i = 0; i < LL; i++) {
        aggk<<<(NN * 32 + 255) / 256, 256>>>(ph, puh, eps_l, i);
        gemm_hmma<1><<<GB, 256, SMEM_HM>>>(puh, pwh + (1 + i) * HH * HH, pwl + (1 + i) * HH * HH,
                                           b1 + i * HH, pzh, nullptr, nullptr, nullptr, nullptr, i);
        gemm_hmma<2><<<GB, 256, SMEM_HM>>>(pzh, pwh + (5 + i) * HH * HH, pwl + (5 + i) * HH * HH,
                                           b2 + i * HH, ph, lng + i * HH, lnb + i * HH,
                                           bng + i * HH, bnb + i * HH, i);
    }

    poolk<<<1000, 128>>>(ph, batch);
    finalk<<<(GG * HH + 255) / 256, 256>>>(out);

    cudaStreamDestroy(s2);
    cudaEventDestroy(evF);
    cudaEventDestroy(evJ);
}